// round 1
// baseline (speedup 1.0000x reference)
#include <cuda_runtime.h>
#include <math.h>

#define BN_EPS 1e-5f

// ---------------- device scratch (no allocations allowed) ----------------
__device__ float g_ef1[16 * 64 * 4096];   // conv1 output  [B, Cq, H, W]
__device__ float g_ef [16 * 64 * 4096];   // conv2 output  [B, Cq, H, W]
__device__ float g_w1t[256 * 9 * 64];     // ec1_w transposed: [(ic*9+tap)*64 + oc]
__device__ float g_w2t[ 64 * 9 * 64];     // ec2_w transposed
__device__ float g_owt[ 64 * 256];        // out_w transposed: [ic*256 + oc]
__device__ float g_sc1[64], g_sh1[64];    // fused bias+BN scale/shift for conv1
__device__ float g_sc2[64], g_sh2[64];
__device__ float g_pool[16 * 320];        // concat(x_pool, e_pool) per batch
__device__ float g_gate[16 * 256];        // sigmoid gate per (b, oc)

// ---------------- packed f32x2 helpers ----------------
__device__ __forceinline__ unsigned long long pack2(float x, float y) {
    unsigned long long r;
    asm("mov.b64 %0, {%1,%2};" : "=l"(r) : "f"(x), "f"(y));
    return r;
}
__device__ __forceinline__ void fma2(unsigned long long& d,
                                     unsigned long long a,
                                     unsigned long long b) {
    asm("fma.rn.f32x2 %0, %1, %2, %0;" : "+l"(d) : "l"(a), "l"(b));
}
__device__ __forceinline__ float2 unpack2(unsigned long long v) {
    float lo, hi;
    asm("mov.b64 {%0,%1}, %2;" : "=f"(lo), "=f"(hi) : "l"(v));
    return make_float2(lo, hi);
}

// ---------------- prep: weight transposes + BN folding ----------------
__global__ void prep_kernel(const float* __restrict__ ec1_w, const float* __restrict__ ec1_b,
                            const float* __restrict__ bn1_g, const float* __restrict__ bn1_b,
                            const float* __restrict__ bn1_m, const float* __restrict__ bn1_v,
                            const float* __restrict__ ec2_w, const float* __restrict__ ec2_b,
                            const float* __restrict__ bn2_g, const float* __restrict__ bn2_b,
                            const float* __restrict__ bn2_m, const float* __restrict__ bn2_v,
                            const float* __restrict__ out_w) {
    int j = blockIdx.x * blockDim.x + threadIdx.x;
    // ec1_w: [64 oc][256 ic][3][3] -> g_w1t[(ic*9+tap)*64 + oc]
    if (j < 256 * 9 * 64) {
        int oc = j & 63;
        int t = j >> 6;          // ic*9+tap, ic in [0,256)
        int ic = t / 9;
        int tap = t - ic * 9;
        g_w1t[j] = ec1_w[(oc * 256 + ic) * 9 + tap];
    }
    if (j < 64 * 9 * 64) {
        int oc = j & 63;
        int t = j >> 6;
        int ic = t / 9;
        int tap = t - ic * 9;
        g_w2t[j] = ec2_w[(oc * 64 + ic) * 9 + tap];
    }
    // out_w: [256 oc][64 ic] -> g_owt[ic*256 + oc]
    if (j < 64 * 256) {
        int oc = j & 255;
        int ic = j >> 8;
        g_owt[j] = out_w[oc * 64 + ic];
    }
    if (j < 64) {
        float inv1 = bn1_g[j] * rsqrtf(bn1_v[j] + BN_EPS);
        g_sc1[j] = inv1;
        g_sh1[j] = ec1_b[j] * inv1 + bn1_b[j] - bn1_m[j] * inv1;
        float inv2 = bn2_g[j] * rsqrtf(bn2_v[j] + BN_EPS);
        g_sc2[j] = inv2;
        g_sh2[j] = ec2_b[j] * inv2 + bn2_b[j] - bn2_m[j] * inv2;
    }
}

// ---------------- fused conv3x3 + BN + ReLU ----------------
// Block = 128 threads = 16x8 pixel tile; each thread accumulates all 64 oc
// (as 32 packed f32x2 pairs). Input tile + transposed weight chunk in smem.
template <int CIN>
__global__ void __launch_bounds__(128, 4)
conv_bn_relu(const float* __restrict__ in, const float* __restrict__ wt,
             const float* __restrict__ scale, const float* __restrict__ shift,
             float* __restrict__ out) {
    __shared__ __align__(16) float s_in[8][10][18];   // 8 ic x (8+2) x (16+2)
    __shared__ __align__(16) float s_w[8 * 9 * 64];   // [(icl*9+tap)*64 + oc]

    const int tid = threadIdx.x;
    const int tx = tid & 15;        // 0..15
    const int ty = tid >> 4;        // 0..7
    const int x0 = blockIdx.x * 16;
    const int y0 = blockIdx.y * 8;
    const int b  = blockIdx.z;

    unsigned long long acc[32];
    const unsigned long long z = pack2(0.f, 0.f);
#pragma unroll
    for (int i = 0; i < 32; i++) acc[i] = z;

    for (int c0 = 0; c0 < CIN; c0 += 8) {
        __syncthreads();
        // load input tile with halo (zero pad at image borders)
        for (int idx = tid; idx < 8 * 10 * 18; idx += 128) {
            int ic = idx / 180;
            int r = idx - ic * 180;
            int ry = r / 18;
            int rx = r - ry * 18;
            int gy = y0 - 1 + ry;
            int gx = x0 - 1 + rx;
            float v = 0.f;
            if ((unsigned)gy < 64u && (unsigned)gx < 64u)
                v = in[(((b * CIN) + (c0 + ic)) << 12) + (gy << 6) + gx];
            s_in[ic][ry][rx] = v;
        }
        // load weight chunk (already in [(ic*9+tap)*64+oc] layout -> contiguous)
        const float* wsrc = wt + c0 * 9 * 64;
        for (int idx = tid; idx < 8 * 9 * 64; idx += 128)
            s_w[idx] = wsrc[idx];
        __syncthreads();

        for (int ic = 0; ic < 8; ic++) {
#pragma unroll
            for (int ky = 0; ky < 3; ky++) {
#pragma unroll
                for (int kx = 0; kx < 3; kx++) {
                    float v = s_in[ic][ty + ky][tx + kx];
                    unsigned long long vv = pack2(v, v);
                    const ulonglong2* wp =
                        (const ulonglong2*)&s_w[((ic * 9) + (ky * 3 + kx)) << 6];
#pragma unroll
                    for (int j = 0; j < 16; j++) {
                        ulonglong2 w2 = wp[j];
                        fma2(acc[2 * j],     vv, w2.x);
                        fma2(acc[2 * j + 1], vv, w2.y);
                    }
                }
            }
        }
    }

    const int gy = y0 + ty, gx = x0 + tx;
    const int pix = (gy << 6) + gx;
#pragma unroll
    for (int i = 0; i < 32; i++) {
        float2 a = unpack2(acc[i]);
        int oc = 2 * i;
        float r0 = fmaxf(a.x * scale[oc]     + shift[oc],     0.f);
        float r1 = fmaxf(a.y * scale[oc + 1] + shift[oc + 1], 0.f);
        out[(((b * 64) + oc)     << 12) + pix] = r0;
        out[(((b * 64) + oc + 1) << 12) + pix] = r1;
    }
}

// ---------------- global average pooling into concat layout ----------------
__global__ void pool_kernel(const float* __restrict__ x, const float* __restrict__ ef) {
    const int c = blockIdx.x;        // 0..319
    const int b = blockIdx.y;
    const int tid = threadIdx.x;     // 128 threads
    const float* src = (c < 256) ? &x[((b << 8) + c) << 12]
                                 : &ef[((b * 64) + (c - 256)) << 12];
    float s = 0.f;
    for (int i = tid; i < 4096; i += 128) s += src[i];
    __shared__ float red[128];
    red[tid] = s;
    __syncthreads();
    for (int o = 64; o > 0; o >>= 1) {
        if (tid < o) red[tid] += red[tid + o];
        __syncthreads();
    }
    if (tid == 0) g_pool[b * 320 + c] = red[0] * (1.f / 4096.f);
}

// ---------------- gate MLP (tiny) ----------------
__global__ void gate_kernel(const float* __restrict__ g1_w, const float* __restrict__ g1_b,
                            const float* __restrict__ gbn_g, const float* __restrict__ gbn_b,
                            const float* __restrict__ gbn_m, const float* __restrict__ gbn_v,
                            const float* __restrict__ g2_w, const float* __restrict__ g2_b) {
    const int b = blockIdx.x;
    const int tid = threadIdx.x;     // 128 threads
    __shared__ float sg[320];
    __shared__ float sh[128];
    for (int i = tid; i < 320; i += 128) sg[i] = g_pool[b * 320 + i];
    __syncthreads();
    // h[j] = relu(bn(g @ g1_w.T + g1_b))
    {
        float s = 0.f;
        const float* wr = g1_w + tid * 320;
        for (int k = 0; k < 320; k++) s = fmaf(wr[k], sg[k], s);
        s += g1_b[tid];
        float inv = gbn_g[tid] * rsqrtf(gbn_v[tid] + BN_EPS);
        s = (s - gbn_m[tid]) * inv + gbn_b[tid];
        sh[tid] = fmaxf(s, 0.f);
    }
    __syncthreads();
    for (int oc = tid; oc < 256; oc += 128) {
        float t = 0.f;
        const float* wr = g2_w + oc * 128;
        for (int k = 0; k < 128; k++) t = fmaf(wr[k], sh[k], t);
        t += g2_b[oc];
        g_gate[b * 256 + oc] = 1.f / (1.f + expf(-t));
    }
}

// ---------------- 1x1 conv (64->256) + gated residual add ----------------
// Block: 256 threads; tile = 64 pixels x all 256 oc (4 groups of 64).
__global__ void out_gemm(const float* __restrict__ ef, const float* __restrict__ x,
                         const float* __restrict__ out_b, float* __restrict__ out) {
    __shared__ __align__(16) float s_ef[64 * 64];   // [ic][px]
    __shared__ __align__(16) float s_w[64 * 64];    // [ic][ocl]
    const int tid = threadIdx.x;
    const int px = tid & 63;
    const int ocq = tid >> 6;       // 0..3  -> handles 16 oc
    const int b = blockIdx.y;
    const int p0 = blockIdx.x * 64;

    for (int idx = tid; idx < 64 * 64; idx += 256) {
        int ic = idx >> 6, p = idx & 63;
        s_ef[(ic << 6) + p] = ef[((b * 64 + ic) << 12) + p0 + p];
    }

    for (int ocg = 0; ocg < 4; ocg++) {
        __syncthreads();
        for (int idx = tid; idx < 64 * 64; idx += 256) {
            int ic = idx >> 6, ocl = idx & 63;
            s_w[(ic << 6) + ocl] = g_owt[(ic << 8) + ocg * 64 + ocl];
        }
        __syncthreads();

        unsigned long long acc[8];
        const unsigned long long z = pack2(0.f, 0.f);
#pragma unroll
        for (int i = 0; i < 8; i++) acc[i] = z;

        for (int ic = 0; ic < 64; ic++) {
            float v = s_ef[(ic << 6) + px];
            unsigned long long vv = pack2(v, v);
            const ulonglong2* wp = (const ulonglong2*)&s_w[(ic << 6) + (ocq << 4)];
#pragma unroll
            for (int j = 0; j < 4; j++) {
                ulonglong2 w2 = wp[j];
                fma2(acc[2 * j],     vv, w2.x);
                fma2(acc[2 * j + 1], vv, w2.y);
            }
        }

#pragma unroll
        for (int i = 0; i < 8; i++) {
            float2 a = unpack2(acc[i]);
            int oc = ocg * 64 + (ocq << 4) + 2 * i;
            {
                int gi = (((b << 8) + oc) << 12) + p0 + px;
                float gate = g_gate[b * 256 + oc];
                out[gi] = x[gi] + gate * (a.x + out_b[oc]);
            }
            {
                int gi = (((b << 8) + oc + 1) << 12) + p0 + px;
                float gate = g_gate[b * 256 + oc + 1];
                out[gi] = x[gi] + gate * (a.y + out_b[oc + 1]);
            }
        }
    }
}

// ---------------- launch ----------------
extern "C" void kernel_launch(void* const* d_in, const int* in_sizes, int n_in,
                              void* d_out, int out_size) {
    const float* x     = (const float*)d_in[0];
    const float* ec1_w = (const float*)d_in[1];
    const float* ec1_b = (const float*)d_in[2];
    const float* bn1_g = (const float*)d_in[3];
    const float* bn1_b = (const float*)d_in[4];
    const float* bn1_m = (const float*)d_in[5];
    const float* bn1_v = (const float*)d_in[6];
    const float* ec2_w = (const float*)d_in[7];
    const float* ec2_b = (const float*)d_in[8];
    const float* bn2_g = (const float*)d_in[9];
    const float* bn2_b = (const float*)d_in[10];
    const float* bn2_m = (const float*)d_in[11];
    const float* bn2_v = (const float*)d_in[12];
    const float* g1_w  = (const float*)d_in[13];
    const float* g1_b  = (const float*)d_in[14];
    const float* gbn_g = (const float*)d_in[15];
    const float* gbn_b = (const float*)d_in[16];
    const float* gbn_m = (const float*)d_in[17];
    const float* gbn_v = (const float*)d_in[18];
    const float* g2_w  = (const float*)d_in[19];
    const float* g2_b  = (const float*)d_in[20];
    const float* out_w = (const float*)d_in[21];
    const float* out_b = (const float*)d_in[22];
    float* out = (float*)d_out;

    float* ef1 = nullptr; float* ef = nullptr;
    cudaGetSymbolAddress((void**)&ef1, g_ef1);
    cudaGetSymbolAddress((void**)&ef,  g_ef);
    float* w1t = nullptr; float* w2t = nullptr;
    cudaGetSymbolAddress((void**)&w1t, g_w1t);
    cudaGetSymbolAddress((void**)&w2t, g_w2t);
    float* sc1 = nullptr; float* sh1 = nullptr; float* sc2 = nullptr; float* sh2 = nullptr;
    cudaGetSymbolAddress((void**)&sc1, g_sc1);
    cudaGetSymbolAddress((void**)&sh1, g_sh1);
    cudaGetSymbolAddress((void**)&sc2, g_sc2);
    cudaGetSymbolAddress((void**)&sh2, g_sh2);

    prep_kernel<<<(256 * 9 * 64 + 255) / 256, 256>>>(
        ec1_w, ec1_b, bn1_g, bn1_b, bn1_m, bn1_v,
        ec2_w, ec2_b, bn2_g, bn2_b, bn2_m, bn2_v, out_w);

    conv_bn_relu<256><<<dim3(4, 8, 16), 128>>>(x,   w1t, sc1, sh1, ef1);
    conv_bn_relu<64> <<<dim3(4, 8, 16), 128>>>(ef1, w2t, sc2, sh2, ef);

    pool_kernel<<<dim3(320, 16), 128>>>(x, ef);
    gate_kernel<<<16, 128>>>(g1_w, g1_b, gbn_g, gbn_b, gbn_m, gbn_v, g2_w, g2_b);

    out_gemm<<<dim3(64, 16), 256>>>(ef, x, out_b, out);
}

// round 3
// speedup vs baseline: 2.1060x; 2.1060x over previous
#include <cuda_runtime.h>
#include <cuda_bf16.h>
#include <cstdint>
#include <math.h>

#define BN_EPS 1e-5f

// ---------------- device scratch (no allocations allowed) ----------------
__device__ float g_ef1[16 * 64 * 4096];   // conv1 output  [B, 64, H, W]
__device__ float g_ef [16 * 64 * 4096];   // conv2 output  [B, 64, H, W]
__device__ __align__(16) __nv_bfloat16 g_w1h[4 * 9 * 64 * 64];  // [g][tap][oc][ic] hi
__device__ __align__(16) __nv_bfloat16 g_w1l[4 * 9 * 64 * 64];  // lo
__device__ __align__(16) __nv_bfloat16 g_w2h[9 * 64 * 64];
__device__ __align__(16) __nv_bfloat16 g_w2l[9 * 64 * 64];
__device__ float g_owt[64 * 256];         // out_w transposed: [ic*256 + oc]
__device__ float g_sc1[64], g_sh1[64];
__device__ float g_sc2[64], g_sh2[64];
__device__ float g_pool[16 * 320];
__device__ float g_gate[16 * 256];

// ---------------- warp-MMA helpers (plain sm_80+ PTX, no 'a' features) ----------------
__device__ __forceinline__ uint32_t smem_to_u32(const void* p) {
    uint32_t a;
    asm("{ .reg .u64 t; cvta.to.shared.u64 t, %1; cvt.u32.u64 %0, t; }" : "=r"(a) : "l"(p));
    return a;
}
__device__ __forceinline__ void ldsm_x4(uint32_t (&r)[4], uint32_t addr) {
    asm volatile("ldmatrix.sync.aligned.m8n8.x4.shared.b16 {%0,%1,%2,%3}, [%4];"
                 : "=r"(r[0]), "=r"(r[1]), "=r"(r[2]), "=r"(r[3]) : "r"(addr));
}
__device__ __forceinline__ void mma16816(float (&c)[4], const uint32_t (&a)[4],
                                         uint32_t b0, uint32_t b1) {
    asm volatile("mma.sync.aligned.m16n8k16.row.col.f32.bf16.bf16.f32 "
                 "{%0,%1,%2,%3}, {%4,%5,%6,%7}, {%8,%9}, {%0,%1,%2,%3};"
                 : "+f"(c[0]), "+f"(c[1]), "+f"(c[2]), "+f"(c[3])
                 : "r"(a[0]), "r"(a[1]), "r"(a[2]), "r"(a[3]), "r"(b0), "r"(b1));
}

// ---------------- packed f32x2 helpers (for out_gemm) ----------------
__device__ __forceinline__ unsigned long long pack2(float x, float y) {
    unsigned long long r;
    asm("mov.b64 %0, {%1,%2};" : "=l"(r) : "f"(x), "f"(y));
    return r;
}
__device__ __forceinline__ void fma2(unsigned long long& d, unsigned long long a,
                                     unsigned long long b) {
    asm("fma.rn.f32x2 %0, %1, %2, %0;" : "+l"(d) : "l"(a), "l"(b));
}
__device__ __forceinline__ float2 unpack2(unsigned long long v) {
    float lo, hi;
    asm("mov.b64 {%0,%1}, %2;" : "=f"(lo), "=f"(hi) : "l"(v));
    return make_float2(lo, hi);
}

// ---------------- prep: weight split + transposes + BN folding ----------------
__global__ void prep_kernel(const float* __restrict__ ec1_w, const float* __restrict__ ec1_b,
                            const float* __restrict__ bn1_g, const float* __restrict__ bn1_b,
                            const float* __restrict__ bn1_m, const float* __restrict__ bn1_v,
                            const float* __restrict__ ec2_w, const float* __restrict__ ec2_b,
                            const float* __restrict__ bn2_g, const float* __restrict__ bn2_b,
                            const float* __restrict__ bn2_m, const float* __restrict__ bn2_v,
                            const float* __restrict__ out_w) {
    int j = blockIdx.x * blockDim.x + threadIdx.x;
    if (j < 4 * 9 * 64 * 64) {           // conv1 weights -> bf16 hi/lo [g][t][oc][ic]
        int icl = j & 63;
        int oc = (j >> 6) & 63;
        int gt = j >> 12;                // 0..35
        int t = gt % 9;
        int g = gt / 9;
        float w = ec1_w[(oc * 256 + (g * 64 + icl)) * 9 + t];
        __nv_bfloat16 h = __float2bfloat16(w);
        g_w1h[j] = h;
        g_w1l[j] = __float2bfloat16(w - __bfloat162float(h));
    }
    if (j < 9 * 64 * 64) {               // conv2 weights
        int icl = j & 63;
        int oc = (j >> 6) & 63;
        int t = j >> 12;                 // 0..8
        float w = ec2_w[(oc * 64 + icl) * 9 + t];
        __nv_bfloat16 h = __float2bfloat16(w);
        g_w2h[j] = h;
        g_w2l[j] = __float2bfloat16(w - __bfloat162float(h));
    }
    if (j < 64 * 256) {                  // out_w transpose
        int oc = j & 255;
        int ic = j >> 8;
        g_owt[j] = out_w[oc * 64 + ic];
    }
    if (j < 64) {
        float inv1 = bn1_g[j] * rsqrtf(bn1_v[j] + BN_EPS);
        g_sc1[j] = inv1;
        g_sh1[j] = ec1_b[j] * inv1 + bn1_b[j] - bn1_m[j] * inv1;
        float inv2 = bn2_g[j] * rsqrtf(bn2_v[j] + BN_EPS);
        g_sc2[j] = inv2;
        g_sh2[j] = ec2_b[j] * inv2 + bn2_b[j] - bn2_m[j] * inv2;
    }
}

// ---------------- HMMA conv3x3 + BN + ReLU ----------------
// smem byte offsets (rows padded to 144B for conflict-free ldmatrix)
static constexpr int TILE_HI = 0;          // [180 px][64 ic] bf16, stride 144
static constexpr int TILE_LO = 25920;
static constexpr int B_HI    = 51840;      // [64 oc][64 ic] bf16, stride 144
static constexpr int B_LO    = 61056;
static constexpr int SC_OFF  = 70272;      // 64 floats
static constexpr int SH_OFF  = 70528;      // 64 floats
static constexpr int SMEM_TOTAL = 70784;

template <int CIN>
__global__ void __launch_bounds__(128, 2)
conv_mma(const float* __restrict__ in,
         const __nv_bfloat16* __restrict__ wh, const __nv_bfloat16* __restrict__ wl,
         const float* __restrict__ scale, const float* __restrict__ shift,
         float* __restrict__ out) {
    extern __shared__ char smem[];
    const uint32_t sb = smem_to_u32(smem);
    const int tid = threadIdx.x;
    const int wid = tid >> 5, lane = tid & 31;
    const int x0 = blockIdx.x * 16, y0 = blockIdx.y * 8, b = blockIdx.z;

    if (tid < 64) {
        ((float*)(smem + SC_OFF))[tid] = scale[tid];
        ((float*)(smem + SH_OFF))[tid] = shift[tid];
    }

    // per-lane ldmatrix bases
    const int arow  = (lane & 7) + ((lane >> 3) & 1) * 8;   // A m-row 0..15
    const int akoff = (lane >> 4) * 8;                      // A k-half
    const int abase0 = ((2 * wid + 0) * 18 + arow) * 144 + akoff * 2;
    const int abase1 = ((2 * wid + 1) * 18 + arow) * 144 + akoff * 2;
    const int nrow  = (lane & 7) + ((lane >> 4) & 1) * 8;   // B n-row 0..15 (pair)
    const int bkoff = ((lane >> 3) & 1) * 8;                // B k-half
    const int bbase = nrow * 144 + bkoff * 2;

    float acc[2][8][4];
#pragma unroll
    for (int i = 0; i < 2; i++)
#pragma unroll
        for (int j = 0; j < 8; j++)
#pragma unroll
            for (int k = 0; k < 4; k++) acc[i][j][k] = 0.f;

    for (int g = 0; g < CIN / 64; g++) {
        __syncthreads();   // previous group's compute (TILE reads) done
        // ---- stage input halo tile, split to bf16 hi/lo ----
        for (int idx = tid; idx < 180 * 64; idx += 128) {
            int ic = idx / 180;
            int p = idx - ic * 180;
            int tr = p / 18;
            int tc = p - tr * 18;
            int gy = y0 - 1 + tr, gx = x0 - 1 + tc;
            float v = 0.f;
            if ((unsigned)gy < 64u && (unsigned)gx < 64u)
                v = in[((size_t)(b * CIN + g * 64 + ic) << 12) + (gy << 6) + gx];
            __nv_bfloat16 h = __float2bfloat16(v);
            __nv_bfloat16 l = __float2bfloat16(v - __bfloat162float(h));
            int off = p * 144 + ic * 2;
            *(__nv_bfloat16*)(smem + TILE_HI + off) = h;
            *(__nv_bfloat16*)(smem + TILE_LO + off) = l;
        }

        for (int t = 0; t < 9; t++) {
            __syncthreads();   // TILE staged (t=0) / previous tap's B reads done (t>0)
            // ---- stage weights for this tap ----
            {
                const uint4* s4h = (const uint4*)(wh + (size_t)(g * 9 + t) * 4096);
                const uint4* s4l = (const uint4*)(wl + (size_t)(g * 9 + t) * 4096);
                for (int m = tid; m < 512; m += 128) {
                    int row = m >> 3, col = m & 7;
                    *(uint4*)(smem + B_HI + row * 144 + col * 16) = s4h[m];
                    *(uint4*)(smem + B_LO + row * 144 + col * 16) = s4l[m];
                }
            }
            __syncthreads();

            const int ky = t / 3, kx = t - ky * 3;
            const int tapoff = (ky * 18 + kx) * 144;
            const uint32_t a0h = sb + TILE_HI + abase0 + tapoff;
            const uint32_t a1h = sb + TILE_HI + abase1 + tapoff;
            const uint32_t a0l = sb + TILE_LO + abase0 + tapoff;
            const uint32_t a1l = sb + TILE_LO + abase1 + tapoff;

#pragma unroll
            for (int ks = 0; ks < 4; ks++) {
                const uint32_t ko = ks * 32;   // 16 ic * 2B
                uint32_t ah0[4], ah1[4], al0[4], al1[4];
                ldsm_x4(ah0, a0h + ko);
                ldsm_x4(ah1, a1h + ko);
                ldsm_x4(al0, a0l + ko);
                ldsm_x4(al1, a1l + ko);
#pragma unroll
                for (int np = 0; np < 4; np++) {
                    uint32_t bh[4], bl[4];
                    ldsm_x4(bh, sb + B_HI + np * 2304 + bbase + ko);
                    ldsm_x4(bl, sb + B_LO + np * 2304 + bbase + ko);
                    mma16816(acc[0][2 * np],     ah0, bh[0], bh[1]);
                    mma16816(acc[0][2 * np + 1], ah0, bh[2], bh[3]);
                    mma16816(acc[1][2 * np],     ah1, bh[0], bh[1]);
                    mma16816(acc[1][2 * np + 1], ah1, bh[2], bh[3]);
                    mma16816(acc[0][2 * np],     ah0, bl[0], bl[1]);
                    mma16816(acc[0][2 * np + 1], ah0, bl[2], bl[3]);
                    mma16816(acc[1][2 * np],     ah1, bl[0], bl[1]);
                    mma16816(acc[1][2 * np + 1], ah1, bl[2], bl[3]);
                    mma16816(acc[0][2 * np],     al0, bh[0], bh[1]);
                    mma16816(acc[0][2 * np + 1], al0, bh[2], bh[3]);
                    mma16816(acc[1][2 * np],     al1, bh[0], bh[1]);
                    mma16816(acc[1][2 * np + 1], al1, bh[2], bh[3]);
                }
            }
        }
    }

    // ---- epilogue: BN + ReLU + store ----
    const float* s_sc = (const float*)(smem + SC_OFF);
    const float* s_sh = (const float*)(smem + SH_OFF);
    const int r0 = lane >> 2;
    const int cc = (lane & 3) * 2;
#pragma unroll
    for (int mt = 0; mt < 2; mt++) {
        const int y = y0 + 2 * wid + mt;
        float* po = out + (((size_t)b * 64) << 12) + (y << 6) + x0;
#pragma unroll
        for (int nt = 0; nt < 8; nt++) {
#pragma unroll
            for (int j = 0; j < 4; j++) {
                int oc = nt * 8 + cc + (j & 1);
                int xo = r0 + (j >> 1) * 8;
                float v = acc[mt][nt][j] * s_sc[oc] + s_sh[oc];
                po[((size_t)oc << 12) + xo] = fmaxf(v, 0.f);
            }
        }
    }
}

// ---------------- global average pooling ----------------
__global__ void pool_kernel(const float* __restrict__ x, const float* __restrict__ ef) {
    const int c = blockIdx.x;
    const int b = blockIdx.y;
    const int tid = threadIdx.x;
    const float* src = (c < 256) ? &x[(size_t)((b << 8) + c) << 12]
                                 : &ef[(size_t)((b * 64) + (c - 256)) << 12];
    float s = 0.f;
    for (int i = tid; i < 4096; i += 128) s += src[i];
    __shared__ float red[128];
    red[tid] = s;
    __syncthreads();
    for (int o = 64; o > 0; o >>= 1) {
        if (tid < o) red[tid] += red[tid + o];
        __syncthreads();
    }
    if (tid == 0) g_pool[b * 320 + c] = red[0] * (1.f / 4096.f);
}

// ---------------- gate MLP ----------------
__global__ void gate_kernel(const float* __restrict__ g1_w, const float* __restrict__ g1_b,
                            const float* __restrict__ gbn_g, const float* __restrict__ gbn_b,
                            const float* __restrict__ gbn_m, const float* __restrict__ gbn_v,
                            const float* __restrict__ g2_w, const float* __restrict__ g2_b) {
    const int b = blockIdx.x;
    const int tid = threadIdx.x;
    __shared__ float sg[320];
    __shared__ float sh[128];
    for (int i = tid; i < 320; i += 128) sg[i] = g_pool[b * 320 + i];
    __syncthreads();
    {
        float s = 0.f;
        const float* wr = g1_w + tid * 320;
        for (int k = 0; k < 320; k++) s = fmaf(wr[k], sg[k], s);
        s += g1_b[tid];
        float inv = gbn_g[tid] * rsqrtf(gbn_v[tid] + BN_EPS);
        s = (s - gbn_m[tid]) * inv + gbn_b[tid];
        sh[tid] = fmaxf(s, 0.f);
    }
    __syncthreads();
    for (int oc = tid; oc < 256; oc += 128) {
        float t = 0.f;
        const float* wr = g2_w + oc * 128;
        for (int k = 0; k < 128; k++) t = fmaf(wr[k], sh[k], t);
        t += g2_b[oc];
        g_gate[b * 256 + oc] = 1.f / (1.f + expf(-t));
    }
}

// ---------------- 1x1 conv (64->256) + gated residual add ----------------
__global__ void out_gemm(const float* __restrict__ ef, const float* __restrict__ x,
                         const float* __restrict__ out_b, float* __restrict__ out) {
    __shared__ __align__(16) float s_ef[64 * 64];
    __shared__ __align__(16) float s_w[64 * 64];
    const int tid = threadIdx.x;
    const int px = tid & 63;
    const int ocq = tid >> 6;
    const int b = blockIdx.y;
    const int p0 = blockIdx.x * 64;

    for (int idx = tid; idx < 64 * 64; idx += 256) {
        int ic = idx >> 6, p = idx & 63;
        s_ef[(ic << 6) + p] = ef[((size_t)(b * 64 + ic) << 12) + p0 + p];
    }

    for (int ocg = 0; ocg < 4; ocg++) {
        __syncthreads();
        for (int idx = tid; idx < 64 * 64; idx += 256) {
            int ic = idx >> 6, ocl = idx & 63;
            s_w[(ic << 6) + ocl] = g_owt[(ic << 8) + ocg * 64 + ocl];
        }
        __syncthreads();

        unsigned long long acc[8];
        const unsigned long long z = pack2(0.f, 0.f);
#pragma unroll
        for (int i = 0; i < 8; i++) acc[i] = z;

        for (int ic = 0; ic < 64; ic++) {
            float v = s_ef[(ic << 6) + px];
            unsigned long long vv = pack2(v, v);
            const ulonglong2* wp = (const ulonglong2*)&s_w[(ic << 6) + (ocq << 4)];
#pragma unroll
            for (int j = 0; j < 4; j++) {
                ulonglong2 w2 = wp[j];
                fma2(acc[2 * j], vv, w2.x);
                fma2(acc[2 * j + 1], vv, w2.y);
            }
        }

#pragma unroll
        for (int i = 0; i < 8; i++) {
            float2 a = unpack2(acc[i]);
            int oc = ocg * 64 + (ocq << 4) + 2 * i;
            {
                size_t gi = ((size_t)((b << 8) + oc) << 12) + p0 + px;
                out[gi] = x[gi] + g_gate[b * 256 + oc] * (a.x + out_b[oc]);
            }
            {
                size_t gi = ((size_t)((b << 8) + oc + 1) << 12) + p0 + px;
                out[gi] = x[gi] + g_gate[b * 256 + oc + 1] * (a.y + out_b[oc + 1]);
            }
        }
    }
}

// ---------------- launch ----------------
extern "C" void kernel_launch(void* const* d_in, const int* in_sizes, int n_in,
                              void* d_out, int out_size) {
    const float* x     = (const float*)d_in[0];
    const float* ec1_w = (const float*)d_in[1];
    const float* ec1_b = (const float*)d_in[2];
    const float* bn1_g = (const float*)d_in[3];
    const float* bn1_b = (const float*)d_in[4];
    const float* bn1_m = (const float*)d_in[5];
    const float* bn1_v = (const float*)d_in[6];
    const float* ec2_w = (const float*)d_in[7];
    const float* ec2_b = (const float*)d_in[8];
    const float* bn2_g = (const float*)d_in[9];
    const float* bn2_b = (const float*)d_in[10];
    const float* bn2_m = (const float*)d_in[11];
    const float* bn2_v = (const float*)d_in[12];
    const float* g1_w  = (const float*)d_in[13];
    const float* g1_b  = (const float*)d_in[14];
    const float* gbn_g = (const float*)d_in[15];
    const float* gbn_b = (const float*)d_in[16];
    const float* gbn_m = (const float*)d_in[17];
    const float* gbn_v = (const float*)d_in[18];
    const float* g2_w  = (const float*)d_in[19];
    const float* g2_b  = (const float*)d_in[20];
    const float* out_w = (const float*)d_in[21];
    const float* out_b = (const float*)d_in[22];
    float* out = (float*)d_out;

    float* ef1; float* ef;
    cudaGetSymbolAddress((void**)&ef1, g_ef1);
    cudaGetSymbolAddress((void**)&ef,  g_ef);
    __nv_bfloat16 *w1h, *w1l, *w2h, *w2l;
    cudaGetSymbolAddress((void**)&w1h, g_w1h);
    cudaGetSymbolAddress((void**)&w1l, g_w1l);
    cudaGetSymbolAddress((void**)&w2h, g_w2h);
    cudaGetSymbolAddress((void**)&w2l, g_w2l);
    float *sc1, *sh1, *sc2, *sh2;
    cudaGetSymbolAddress((void**)&sc1, g_sc1);
    cudaGetSymbolAddress((void**)&sh1, g_sh1);
    cudaGetSymbolAddress((void**)&sc2, g_sc2);
    cudaGetSymbolAddress((void**)&sh2, g_sh2);

    cudaFuncSetAttribute(conv_mma<256>, cudaFuncAttributeMaxDynamicSharedMemorySize, SMEM_TOTAL);
    cudaFuncSetAttribute(conv_mma<64>,  cudaFuncAttributeMaxDynamicSharedMemorySize, SMEM_TOTAL);

    prep_kernel<<<576, 256>>>(ec1_w, ec1_b, bn1_g, bn1_b, bn1_m, bn1_v,
                              ec2_w, ec2_b, bn2_g, bn2_b, bn2_m, bn2_v, out_w);

    conv_mma<256><<<dim3(4, 8, 16), 128, SMEM_TOTAL>>>(x,   w1h, w1l, sc1, sh1, ef1);
    conv_mma<64> <<<dim3(4, 8, 16), 128, SMEM_TOTAL>>>(ef1, w2h, w2l, sc2, sh2, ef);

    pool_kernel<<<dim3(320, 16), 128>>>(x, ef);
    gate_kernel<<<16, 128>>>(g1_w, g1_b, gbn_g, gbn_b, gbn_m, gbn_v, g2_w, g2_b);

    out_gemm<<<dim3(64, 16), 256>>>(ef, x, out_b, out);
}

// round 6
// speedup vs baseline: 2.3428x; 1.1124x over previous
#include <cuda_runtime.h>
#include <cuda_bf16.h>
#include <cstdint>
#include <math.h>

#define BN_EPS 1e-5f

// ---------------- device scratch (no allocations allowed) ----------------
__device__ __align__(16) float g_xt [16 * 4 * 4096 * 64]; // x transposed: [b][g][px][64ic] tf32, perm
__device__ __align__(16) float g_ef1[16 * 4096 * 64];     // conv1 out, same layout (1 group), perm
__device__ __align__(16) float g_ef [16 * 64 * 4096];     // conv2 out  [b][oc][px] fp32 std
__device__ __align__(16) float g_w1t[4 * 9 * 64 * 64];    // [g][t][oc][64ic perm] tf32
__device__ __align__(16) float g_w2t[9 * 64 * 64];
__device__ float g_owt[64 * 256];                         // out_w transposed: [ic*256 + oc]
__device__ float g_sc1[64], g_sh1[64];
__device__ float g_sc2[64], g_sh2[64];
__device__ float g_pool[16 * 320];
__device__ float g_gate[16 * 256];

// channel permutation within 8-blocks: pos(k) = k<4 ? 2k : 2(k-4)+1
// makes fragment pairs (k, k+4) adjacent -> LDS.64

__device__ __forceinline__ float tf32r(float x) {
    uint32_t u;
    asm("cvt.rna.tf32.f32 %0, %1;" : "=r"(u) : "f"(x));
    return __uint_as_float(u);
}
__device__ __forceinline__ uint32_t fu(float x) { return __float_as_uint(x); }

__device__ __forceinline__ void mma_tf32(float (&c)[4], uint32_t a0, uint32_t a1,
                                         uint32_t a2, uint32_t a3, uint32_t b0, uint32_t b1) {
    asm volatile("mma.sync.aligned.m16n8k8.row.col.f32.tf32.tf32.f32 "
                 "{%0,%1,%2,%3}, {%4,%5,%6,%7}, {%8,%9}, {%0,%1,%2,%3};"
                 : "+f"(c[0]), "+f"(c[1]), "+f"(c[2]), "+f"(c[3])
                 : "r"(a0), "r"(a1), "r"(a2), "r"(a3), "r"(b0), "r"(b1));
}

// ---------------- packed f32x2 helpers (for out_gemm) ----------------
__device__ __forceinline__ unsigned long long pack2(float x, float y) {
    unsigned long long r;
    asm("mov.b64 %0, {%1,%2};" : "=l"(r) : "f"(x), "f"(y));
    return r;
}
__device__ __forceinline__ void fma2(unsigned long long& d, unsigned long long a,
                                     unsigned long long b) {
    asm("fma.rn.f32x2 %0, %1, %2, %0;" : "+l"(d) : "l"(a), "l"(b));
}
__device__ __forceinline__ float2 unpack2(unsigned long long v) {
    float lo, hi;
    asm("mov.b64 {%0,%1}, %2;" : "=f"(lo), "=f"(hi) : "l"(v));
    return make_float2(lo, hi);
}

// ---------------- prep: weight transpose (perm, tf32) + BN folding ----------------
__global__ void prep_kernel(const float* __restrict__ ec1_w, const float* __restrict__ ec1_b,
                            const float* __restrict__ bn1_g, const float* __restrict__ bn1_b,
                            const float* __restrict__ bn1_m, const float* __restrict__ bn1_v,
                            const float* __restrict__ ec2_w, const float* __restrict__ ec2_b,
                            const float* __restrict__ bn2_g, const float* __restrict__ bn2_b,
                            const float* __restrict__ bn2_m, const float* __restrict__ bn2_v,
                            const float* __restrict__ out_w) {
    int j = blockIdx.x * blockDim.x + threadIdx.x;
    if (j < 4 * 9 * 64 * 64) {           // g_w1t[g][t][oc][pos]
        int pos = j & 63;
        int oc = (j >> 6) & 63;
        int gt = j >> 12;                // 0..35
        int t = gt % 9;
        int g = gt / 9;
        int p3 = pos & 7;
        int c3 = (p3 & 1) ? (p3 >> 1) + 4 : (p3 >> 1);   // inverse perm
        int ic = g * 64 + (pos & ~7) + c3;
        g_w1t[j] = tf32r(ec1_w[(oc * 256 + ic) * 9 + t]);
    }
    if (j < 9 * 64 * 64) {               // g_w2t[t][oc][pos]
        int pos = j & 63;
        int oc = (j >> 6) & 63;
        int t = j >> 12;
        int p3 = pos & 7;
        int c3 = (p3 & 1) ? (p3 >> 1) + 4 : (p3 >> 1);
        int ic = (pos & ~7) + c3;
        g_w2t[j] = tf32r(ec2_w[(oc * 64 + ic) * 9 + t]);
    }
    if (j < 64 * 256) {                  // out_w transpose
        int oc = j & 255;
        int ic = j >> 8;
        g_owt[j] = out_w[oc * 64 + ic];
    }
    if (j < 64) {
        float inv1 = bn1_g[j] * rsqrtf(bn1_v[j] + BN_EPS);
        g_sc1[j] = inv1;
        g_sh1[j] = ec1_b[j] * inv1 + bn1_b[j] - bn1_m[j] * inv1;
        float inv2 = bn2_g[j] * rsqrtf(bn2_v[j] + BN_EPS);
        g_sc2[j] = inv2;
        g_sh2[j] = ec2_b[j] * inv2 + bn2_b[j] - bn2_m[j] * inv2;
    }
}

// ---------------- input transpose: x [b][c][px] -> g_xt [b][g][px][64 perm] tf32 ----------------
__global__ void xt_kernel(const float* __restrict__ x, int b_base) {
    __shared__ float s[64 * 129];
    const int ch = blockIdx.x;           // px chunk (128 px)
    const int g = blockIdx.y;
    const int b = b_base + blockIdx.z;
    const int tid = threadIdx.x;         // 256
    for (int idx = tid; idx < 64 * 128; idx += 256) {
        int ic = idx >> 7, px = idx & 127;
        s[ic * 129 + px] = x[((size_t)(b * 256 + g * 64 + ic) << 12) + ch * 128 + px];
    }
    __syncthreads();
    float* dst = g_xt + ((size_t)(b * 4 + g) * 4096 + ch * 128) * 64;
    for (int j = tid; j < 128 * 32; j += 256) {
        int px = j >> 5, pr = j & 31;
        int blk = pr >> 2, kk = pr & 3;
        int c0 = blk * 8 + kk;
        float2 v;
        v.x = tf32r(s[c0 * 129 + px]);
        v.y = tf32r(s[(c0 + 4) * 129 + px]);
        *(float2*)(dst + px * 64 + blk * 8 + 2 * kk) = v;
    }
}

// ---------------- tf32 HMMA conv3x3 + BN + ReLU ----------------
// smem: A [180 px][72 floats] + B [64 oc][72 floats] + sc/sh
static constexpr int A_OFF = 0;                        // floats, stride 72 (288B rows)
static constexpr int B_OFF = 180 * 72;                 // 12960
static constexpr int SC_OFF = B_OFF + 64 * 72;         // 17568
static constexpr int SH_OFF = SC_OFF + 64;             // 17632
static constexpr int SMEM_TOTAL = (SH_OFF + 64) * 4;   // 70784 B

template <int GROUPS, bool PERM_OUT>
__global__ void __launch_bounds__(128, 3)
conv_mma(const float* __restrict__ xt, const float* __restrict__ wt,
         const float* __restrict__ scale, const float* __restrict__ shift,
         float* __restrict__ out) {
    extern __shared__ float smem[];
    float* sA = smem + A_OFF;
    float* sB = smem + B_OFF;
    const int tid = threadIdx.x;
    const int wid = tid >> 5, lane = tid & 31;
    const int x0 = blockIdx.x * 16, y0 = blockIdx.y * 8, b = blockIdx.z;

    if (tid < 64) {
        smem[SC_OFF + tid] = scale[tid];
        smem[SH_OFF + tid] = shift[tid];
    }

    float acc[2][8][4];
#pragma unroll
    for (int i = 0; i < 2; i++)
#pragma unroll
        for (int j = 0; j < 8; j++)
#pragma unroll
            for (int k = 0; k < 4; k++) acc[i][j][k] = 0.f;

    const int lg = lane >> 2;            // groupID 0..7
    const int lk2 = (lane & 3) * 2;      // fragment pair column

    for (int g = 0; g < GROUPS; g++) {
        __syncthreads();                 // previous group's A reads done
        // ---- stage A halo tile: pure uint4 copies ----
        const float* srcb = xt + ((size_t)(b * GROUPS + g) * 4096) * 64;
        for (int m = tid; m < 2880; m += 128) {
            int p = m >> 4, c = m & 15;
            int tr = p / 18, tc = p - tr * 18;
            int gy = y0 - 1 + tr, gx = x0 - 1 + tc;
            uint4 v = make_uint4(0, 0, 0, 0);
            if ((unsigned)gy < 64u && (unsigned)gx < 64u)
                v = *(const uint4*)(srcb + ((gy << 6) + gx) * 64 + c * 4);
            *(uint4*)(sA + p * 72 + c * 4) = v;
        }

        for (int t = 0; t < 9; t++) {
            __syncthreads();             // A staged / prev tap's B reads done
            const uint4* wsrc = (const uint4*)(wt + (size_t)(g * 9 + t) * 4096);
            for (int m = tid; m < 1024; m += 128) {
                int row = m >> 4, c = m & 15;
                *(uint4*)(sB + row * 72 + c * 4) = wsrc[m];
            }
            __syncthreads();

            const int ky = t / 3, kx = t - 3 * ky;
            const int bp0 = (2 * wid + ky) * 18 + kx;
            const float* pA0 = sA + (bp0 + lg) * 72 + lk2;        // m-tile 0
            const float* pA1 = pA0 + 18 * 72;                      // m-tile 1 (next y row)
            const float* pB = sB + lg * 72 + lk2;

#pragma unroll
            for (int kb = 0; kb < 8; kb++) {
                const int ko = kb * 8;
                float2 a00 = *(const float2*)(pA0 + ko);           // rows lg,   cols k,k+4
                float2 a01 = *(const float2*)(pA0 + 8 * 72 + ko);  // rows lg+8
                float2 a10 = *(const float2*)(pA1 + ko);
                float2 a11 = *(const float2*)(pA1 + 8 * 72 + ko);
#pragma unroll
                for (int n8 = 0; n8 < 8; n8++) {
                    float2 bb = *(const float2*)(pB + n8 * 8 * 72 + ko);
                    mma_tf32(acc[0][n8], fu(a00.x), fu(a01.x), fu(a00.y), fu(a01.y),
                             fu(bb.x), fu(bb.y));
                    mma_tf32(acc[1][n8], fu(a10.x), fu(a11.x), fu(a10.y), fu(a11.y),
                             fu(bb.x), fu(bb.y));
                }
            }
        }
    }

    // ---- epilogue: BN + ReLU + store ----
    const float* s_sc = smem + SC_OFF;
    const float* s_sh = smem + SH_OFF;
    const int r0 = lane >> 2;
    const int cc = (lane & 3) * 2;
#pragma unroll
    for (int mt = 0; mt < 2; mt++) {
        const int y = y0 + 2 * wid + mt;
        if (PERM_OUT) {
            float* ob = out + ((size_t)b * 4096 + (y << 6) + x0) * 64;
#pragma unroll
            for (int nt = 0; nt < 8; nt++) {
#pragma unroll
                for (int j = 0; j < 4; j++) {
                    int oc = nt * 8 + cc + (j & 1);
                    int xo = r0 + (j >> 1) * 8;
                    float v = fmaxf(acc[mt][nt][j] * s_sc[oc] + s_sh[oc], 0.f);
                    int p3 = oc & 7;
                    int pp = (oc & ~7) | ((p3 < 4) ? 2 * p3 : 2 * (p3 - 4) + 1);
                    ob[(size_t)xo * 64 + pp] = tf32r(v);
                }
            }
        } else {
            float* po = out + (((size_t)b * 64) << 12) + (y << 6) + x0;
#pragma unroll
            for (int nt = 0; nt < 8; nt++) {
#pragma unroll
                for (int j = 0; j < 4; j++) {
                    int oc = nt * 8 + cc + (j & 1);
                    int xo = r0 + (j >> 1) * 8;
                    float v = acc[mt][nt][j] * s_sc[oc] + s_sh[oc];
                    po[((size_t)oc << 12) + xo] = fmaxf(v, 0.f);
                }
            }
        }
    }
}

// ---------------- global average pooling ----------------
__global__ void pool_kernel(const float* __restrict__ x, const float* __restrict__ ef) {
    const int c = blockIdx.x;
    const int b = blockIdx.y;
    const int tid = threadIdx.x;
    const float* src = (c < 256) ? &x[(size_t)((b << 8) + c) << 12]
                                 : &ef[(size_t)((b * 64) + (c - 256)) << 12];
    float s = 0.f;
    for (int i = tid; i < 4096; i += 128) s += src[i];
    __shared__ float red[128];
    red[tid] = s;
    __syncthreads();
    for (int o = 64; o > 0; o >>= 1) {
        if (tid < o) red[tid] += red[tid + o];
        __syncthreads();
    }
    if (tid == 0) g_pool[b * 320 + c] = red[0] * (1.f / 4096.f);
}

// ---------------- gate MLP ----------------
__global__ void gate_kernel(const float* __restrict__ g1_w, const float* __restrict__ g1_b,
                            const float* __restrict__ gbn_g, const float* __restrict__ gbn_b,
                            const float* __restrict__ gbn_m, const float* __restrict__ gbn_v,
                            const float* __restrict__ g2_w, const float* __restrict__ g2_b) {
    const int b = blockIdx.x;
    const int tid = threadIdx.x;
    __shared__ float sg[320];
    __shared__ float sh[128];
    for (int i = tid; i < 320; i += 128) sg[i] = g_pool[b * 320 + i];
    __syncthreads();
    {
        float s = 0.f;
        const float* wr = g1_w + tid * 320;
        for (int k = 0; k < 320; k++) s = fmaf(wr[k], sg[k], s);
        s += g1_b[tid];
        float inv = gbn_g[tid] * rsqrtf(gbn_v[tid] + BN_EPS);
        s = (s - gbn_m[tid]) * inv + gbn_b[tid];
        sh[tid] = fmaxf(s, 0.f);
    }
    __syncthreads();
    for (int oc = tid; oc < 256; oc += 128) {
        float t = 0.f;
        const float* wr = g2_w + oc * 128;
        for (int k = 0; k < 128; k++) t = fmaf(wr[k], sh[k], t);
        t += g2_b[oc];
        g_gate[b * 256 + oc] = 1.f / (1.f + expf(-t));
    }
}

// ---------------- 1x1 conv (64->256) + gated residual add ----------------
__global__ void out_gemm(const float* __restrict__ ef, const float* __restrict__ x,
                         const float* __restrict__ out_b, float* __restrict__ out) {
    __shared__ __align__(16) float s_ef[64 * 64];
    __shared__ __align__(16) float s_w[64 * 64];
    const int tid = threadIdx.x;
    const int px = tid & 63;
    const int ocq = tid >> 6;
    const int b = blockIdx.y;
    const int p0 = blockIdx.x * 64;

    for (int idx = tid; idx < 64 * 64; idx += 256) {
        int ic = idx >> 6, p = idx & 63;
        s_ef[(ic << 6) + p] = ef[((size_t)(b * 64 + ic) << 12) + p0 + p];
    }

    for (int ocg = 0; ocg < 4; ocg++) {
        __syncthreads();
        for (int idx = tid; idx < 64 * 64; idx += 256) {
            int ic = idx >> 6, ocl = idx & 63;
            s_w[(ic << 6) + ocl] = g_owt[(ic << 8) + ocg * 64 + ocl];
        }
        __syncthreads();

        unsigned long long acc[8];
        const unsigned long long z = pack2(0.f, 0.f);
#pragma unroll
        for (int i = 0; i < 8; i++) acc[i] = z;

        for (int ic = 0; ic < 64; ic++) {
            float v = s_ef[(ic << 6) + px];
            unsigned long long vv = pack2(v, v);
            const ulonglong2* wp = (const ulonglong2*)&s_w[(ic << 6) + (ocq << 4)];
#pragma unroll
            for (int j = 0; j < 4; j++) {
                ulonglong2 w2 = wp[j];
                fma2(acc[2 * j], vv, w2.x);
                fma2(acc[2 * j + 1], vv, w2.y);
            }
        }

#pragma unroll
        for (int i = 0; i < 8; i++) {
            float2 a = unpack2(acc[i]);
            int oc = ocg * 64 + (ocq << 4) + 2 * i;
            {
                size_t gi = ((size_t)((b << 8) + oc) << 12) + p0 + px;
                out[gi] = x[gi] + g_gate[b * 256 + oc] * (a.x + out_b[oc]);
            }
            {
                size_t gi = ((size_t)((b << 8) + oc + 1) << 12) + p0 + px;
                out[gi] = x[gi] + g_gate[b * 256 + oc + 1] * (a.y + out_b[oc + 1]);
            }
        }
    }
}

// ---------------- launch ----------------
extern "C" void kernel_launch(void* const* d_in, const int* in_sizes, int n_in,
                              void* d_out, int out_size) {
    const float* x     = (const float*)d_in[0];
    const float* ec1_w = (const float*)d_in[1];
    const float* ec1_b = (const float*)d_in[2];
    const float* bn1_g = (const float*)d_in[3];
    const float* bn1_b = (const float*)d_in[4];
    const float* bn1_m = (const float*)d_in[5];
    const float* bn1_v = (const float*)d_in[6];
    const float* ec2_w = (const float*)d_in[7];
    const float* ec2_b = (const float*)d_in[8];
    const float* bn2_g = (const float*)d_in[9];
    const float* bn2_b = (const float*)d_in[10];
    const float* bn2_m = (const float*)d_in[11];
    const float* bn2_v = (const float*)d_in[12];
    const float* g1_w  = (const float*)d_in[13];
    const float* g1_b  = (const float*)d_in[14];
    const float* gbn_g = (const float*)d_in[15];
    const float* gbn_b = (const float*)d_in[16];
    const float* gbn_m = (const float*)d_in[17];
    const float* gbn_v = (const float*)d_in[18];
    const float* g2_w  = (const float*)d_in[19];
    const float* g2_b  = (const float*)d_in[20];
    const float* out_w = (const float*)d_in[21];
    const float* out_b = (const float*)d_in[22];
    float* out = (float*)d_out;

    float *xt, *ef1, *ef, *w1t, *w2t;
    cudaGetSymbolAddress((void**)&xt,  g_xt);
    cudaGetSymbolAddress((void**)&ef1, g_ef1);
    cudaGetSymbolAddress((void**)&ef,  g_ef);
    cudaGetSymbolAddress((void**)&w1t, g_w1t);
    cudaGetSymbolAddress((void**)&w2t, g_w2t);
    float *sc1, *sh1, *sc2, *sh2;
    cudaGetSymbolAddress((void**)&sc1, g_sc1);
    cudaGetSymbolAddress((void**)&sh1, g_sh1);
    cudaGetSymbolAddress((void**)&sc2, g_sc2);
    cudaGetSymbolAddress((void**)&sh2, g_sh2);

    cudaFuncSetAttribute(conv_mma<4, true>,
                         cudaFuncAttributeMaxDynamicSharedMemorySize, SMEM_TOTAL);
    cudaFuncSetAttribute(conv_mma<1, false>,
                         cudaFuncAttributeMaxDynamicSharedMemorySize, SMEM_TOTAL);

    // 1: prep
    prep_kernel<<<576, 256>>>(ec1_w, ec1_b, bn1_g, bn1_b, bn1_m, bn1_v,
                              ec2_w, ec2_b, bn2_g, bn2_b, bn2_m, bn2_v, out_w);
    // 2-3: input transpose (split so conv1 lands on the ncu capture slot)
    xt_kernel<<<dim3(32, 4, 8), 256>>>(x, 0);
    xt_kernel<<<dim3(32, 4, 8), 256>>>(x, 8);
    // 4: conv1 (tf32 MMA) -> ef1 (perm layout)
    conv_mma<4, true><<<dim3(4, 8, 16), 128, SMEM_TOTAL>>>(xt, w1t, sc1, sh1, ef1);
    // 5: conv2 -> ef (std layout)
    conv_mma<1, false><<<dim3(4, 8, 16), 128, SMEM_TOTAL>>>(ef1, w2t, sc2, sh2, ef);
    // 6-8: pool, gate, output
    pool_kernel<<<dim3(320, 16), 128>>>(x, ef);
    gate_kernel<<<16, 128>>>(g1_w, g1_b, gbn_g, gbn_b, gbn_m, gbn_v, g2_w, g2_b);
    out_gemm<<<dim3(64, 16), 256>>>(ef, x, out_b, out);
}

// round 7
// speedup vs baseline: 2.5722x; 1.0979x over previous
#include <cuda_runtime.h>
#include <cuda_bf16.h>
#include <cstdint>
#include <math.h>

#define BN_EPS 1e-5f

// ---------------- device scratch (no allocations allowed) ----------------
__device__ __align__(16) float g_xt [16 * 4 * 4096 * 64]; // x transposed: [b][g][px][64ic] tf32, perm
__device__ __align__(16) float g_ef1[16 * 4096 * 64];     // conv1 out, same layout (1 group), perm
__device__ __align__(16) float g_ef [16 * 64 * 4096];     // conv2 out  [b][oc][px] fp32 std
__device__ __align__(16) float g_w1t[4 * 9 * 64 * 64];    // [g][t][oc][64ic perm] tf32
__device__ __align__(16) float g_w2t[9 * 64 * 64];
__device__ float g_owt[64 * 256];                         // out_w transposed: [ic*256 + oc]
__device__ float g_sc1[64], g_sh1[64];
__device__ float g_sc2[64], g_sh2[64];
__device__ float g_pool[16 * 320];
__device__ float g_gate[16 * 256];

// channel permutation within 8-blocks: pos(k) = k<4 ? 2k : 2(k-4)+1
// makes fragment pairs (k, k+4) adjacent -> LDS.64

__device__ __forceinline__ float tf32r(float x) {
    uint32_t u;
    asm("cvt.rna.tf32.f32 %0, %1;" : "=r"(u) : "f"(x));
    return __uint_as_float(u);
}
__device__ __forceinline__ uint32_t fu(float x) { return __float_as_uint(x); }

__device__ __forceinline__ uint32_t smem_u32(const void* p) {
    uint32_t a;
    asm("{ .reg .u64 t; cvta.to.shared.u64 t, %1; cvt.u32.u64 %0, t; }" : "=r"(a) : "l"(p));
    return a;
}

#define CP_ASYNC16(dst_u32, src_ptr) \
    asm volatile("cp.async.cg.shared.global [%0], [%1], 16;" :: "r"(dst_u32), "l"(src_ptr))
#define CP_COMMIT() asm volatile("cp.async.commit_group;" ::: "memory")
#define CP_WAIT0()  asm volatile("cp.async.wait_group 0;" ::: "memory")

__device__ __forceinline__ void mma_tf32(float (&c)[4], uint32_t a0, uint32_t a1,
                                         uint32_t a2, uint32_t a3, uint32_t b0, uint32_t b1) {
    asm volatile("mma.sync.aligned.m16n8k8.row.col.f32.tf32.tf32.f32 "
                 "{%0,%1,%2,%3}, {%4,%5,%6,%7}, {%8,%9}, {%0,%1,%2,%3};"
                 : "+f"(c[0]), "+f"(c[1]), "+f"(c[2]), "+f"(c[3])
                 : "r"(a0), "r"(a1), "r"(a2), "r"(a3), "r"(b0), "r"(b1));
}

// ---------------- packed f32x2 helpers (for out_gemm) ----------------
__device__ __forceinline__ unsigned long long pack2(float x, float y) {
    unsigned long long r;
    asm("mov.b64 %0, {%1,%2};" : "=l"(r) : "f"(x), "f"(y));
    return r;
}
__device__ __forceinline__ void fma2(unsigned long long& d, unsigned long long a,
                                     unsigned long long b) {
    asm("fma.rn.f32x2 %0, %1, %2, %0;" : "+l"(d) : "l"(a), "l"(b));
}
__device__ __forceinline__ float2 unpack2(unsigned long long v) {
    float lo, hi;
    asm("mov.b64 {%0,%1}, %2;" : "=f"(lo), "=f"(hi) : "l"(v));
    return make_float2(lo, hi);
}

// ---------------- prep: weight transpose (perm, tf32) + BN folding ----------------
__global__ void prep_kernel(const float* __restrict__ ec1_w, const float* __restrict__ ec1_b,
                            const float* __restrict__ bn1_g, const float* __restrict__ bn1_b,
                            const float* __restrict__ bn1_m, const float* __restrict__ bn1_v,
                            const float* __restrict__ ec2_w, const float* __restrict__ ec2_b,
                            const float* __restrict__ bn2_g, const float* __restrict__ bn2_b,
                            const float* __restrict__ bn2_m, const float* __restrict__ bn2_v,
                            const float* __restrict__ out_w) {
    int j = blockIdx.x * blockDim.x + threadIdx.x;
    if (j < 4 * 9 * 64 * 64) {           // g_w1t[g][t][oc][pos]
        int pos = j & 63;
        int oc = (j >> 6) & 63;
        int gt = j >> 12;                // 0..35
        int t = gt % 9;
        int g = gt / 9;
        int p3 = pos & 7;
        int c3 = (p3 & 1) ? (p3 >> 1) + 4 : (p3 >> 1);   // inverse perm
        int ic = g * 64 + (pos & ~7) + c3;
        g_w1t[j] = tf32r(ec1_w[(oc * 256 + ic) * 9 + t]);
    }
    if (j < 9 * 64 * 64) {               // g_w2t[t][oc][pos]
        int pos = j & 63;
        int oc = (j >> 6) & 63;
        int t = j >> 12;
        int p3 = pos & 7;
        int c3 = (p3 & 1) ? (p3 >> 1) + 4 : (p3 >> 1);
        int ic = (pos & ~7) + c3;
        g_w2t[j] = tf32r(ec2_w[(oc * 64 + ic) * 9 + t]);
    }
    if (j < 64 * 256) {                  // out_w transpose
        int oc = j & 255;
        int ic = j >> 8;
        g_owt[j] = out_w[oc * 64 + ic];
    }
    if (j < 64) {
        float inv1 = bn1_g[j] * rsqrtf(bn1_v[j] + BN_EPS);
        g_sc1[j] = inv1;
        g_sh1[j] = ec1_b[j] * inv1 + bn1_b[j] - bn1_m[j] * inv1;
        float inv2 = bn2_g[j] * rsqrtf(bn2_v[j] + BN_EPS);
        g_sc2[j] = inv2;
        g_sh2[j] = ec2_b[j] * inv2 + bn2_b[j] - bn2_m[j] * inv2;
    }
}

// ---------------- input transpose: x [b][c][px] -> g_xt [b][g][px][64 perm] tf32 ----------------
__global__ void xt_kernel(const float* __restrict__ x, int b_base) {
    __shared__ float s[64 * 129];
    const int ch = blockIdx.x;           // px chunk (128 px)
    const int g = blockIdx.y;
    const int b = b_base + blockIdx.z;
    const int tid = threadIdx.x;         // 256
    for (int idx = tid; idx < 64 * 128; idx += 256) {
        int ic = idx >> 7, px = idx & 127;
        s[ic * 129 + px] = x[((size_t)(b * 256 + g * 64 + ic) << 12) + ch * 128 + px];
    }
    __syncthreads();
    float* dst = g_xt + ((size_t)(b * 4 + g) * 4096 + ch * 128) * 64;
    for (int j = tid; j < 128 * 32; j += 256) {
        int px = j >> 5, pr = j & 31;
        int blk = pr >> 2, kk = pr & 3;
        int c0 = blk * 8 + kk;
        float2 v;
        v.x = tf32r(s[c0 * 129 + px]);
        v.y = tf32r(s[(c0 + 4) * 129 + px]);
        *(float2*)(dst + px * 64 + blk * 8 + 2 * kk) = v;
    }
}

// ---------------- tf32 HMMA conv3x3 + BN + ReLU (ic-chunked, cp.async pipelined) ----------------
// smem (floats): A [180 px][36] | B0 [64 oc][36] | B1 [64 oc][36] | sc | sh
static constexpr int A_OFF  = 0;
static constexpr int B0_OFF = 180 * 36;                 // 6480
static constexpr int B1_OFF = B0_OFF + 64 * 36;         // 8784
static constexpr int SC_OFF = B1_OFF + 64 * 36;         // 11088
static constexpr int SH_OFF = SC_OFF + 64;              // 11152
static constexpr int SMEM_TOTAL = (SH_OFF + 64) * 4;    // 44864 B

template <int GROUPS, bool PERM_OUT>
__global__ void __launch_bounds__(128, 4)
conv_mma(const float* __restrict__ xt, const float* __restrict__ wt,
         const float* __restrict__ scale, const float* __restrict__ shift,
         float* __restrict__ out) {
    extern __shared__ float smem[];
    const uint32_t s32 = smem_u32(smem);
    float* sA = smem + A_OFF;
    const int tid = threadIdx.x;
    const int wid = tid >> 5, lane = tid & 31;
    const int x0 = blockIdx.x * 16, y0 = blockIdx.y * 8, b = blockIdx.z;

    if (tid < 64) {
        smem[SC_OFF + tid] = scale[tid];
        smem[SH_OFF + tid] = shift[tid];
    }

    float acc[2][8][4];
#pragma unroll
    for (int i = 0; i < 2; i++)
#pragma unroll
        for (int j = 0; j < 8; j++)
#pragma unroll
            for (int k = 0; k < 4; k++) acc[i][j][k] = 0.f;

    const int lg = lane >> 2;            // 0..7
    const int lk2 = (lane & 3) * 2;

    for (int ci = 0; ci < GROUPS * 2; ci++) {
        const int g = ci >> 1, h = ci & 1;
        const float* wbase = wt + (size_t)(g * 9) * 4096 + h * 32;

        // ---- stage A half-chunk [180 px][32 ic] via cp.async (zeros for halo OOB) ----
        const float* srcb = xt + ((size_t)(b * GROUPS + g) * 4096) * 64 + h * 32;
        for (int m = tid; m < 1440; m += 128) {
            int p = m >> 3, c = m & 7;
            int tr = p / 18, tc = p - tr * 18;
            int gy = y0 - 1 + tr, gx = x0 - 1 + tc;
            uint32_t dst = s32 + (uint32_t)(p * 36 + c * 4) * 4;
            if ((unsigned)gy < 64u && (unsigned)gx < 64u) {
                CP_ASYNC16(dst, srcb + ((gy << 6) + gx) * 64 + c * 4);
            } else {
                *(uint4*)((char*)smem + (size_t)(p * 36 + c * 4) * 4) = make_uint4(0, 0, 0, 0);
            }
        }
        // ---- stage B(t=0) into buffer 0 ----
        for (int m = tid; m < 512; m += 128) {
            int row = m >> 3, c = m & 7;
            CP_ASYNC16(s32 + (uint32_t)(B0_OFF + row * 36 + c * 4) * 4,
                       wbase + row * 64 + c * 4);
        }
        CP_COMMIT();
        CP_WAIT0();
        __syncthreads();

        for (int t = 0; t < 9; t++) {
            const int cur = t & 1;
            // ---- prefetch B(t+1) into the other buffer ----
            if (t < 8) {
                const float* wsrc = wbase + (size_t)(t + 1) * 4096;
                const uint32_t bdst = s32 + (uint32_t)((cur ? B0_OFF : B1_OFF)) * 4;
#pragma unroll
                for (int m = tid; m < 512; m += 128) {
                    int row = m >> 3, c = m & 7;
                    CP_ASYNC16(bdst + (uint32_t)(row * 36 + c * 4) * 4,
                               wsrc + row * 64 + c * 4);
                }
                CP_COMMIT();
            }

            // ---- MMAs on B(cur) ----
            const int ky = t / 3, kx = t - 3 * ky;
            const float* pA0 = sA + ((2 * wid + ky) * 18 + kx + lg) * 36 + lk2;
            const float* pA1 = pA0 + 18 * 36;
            const float* pB = smem + (cur ? B1_OFF : B0_OFF) + lg * 36 + lk2;

#pragma unroll
            for (int kb = 0; kb < 4; kb++) {
                const int ko = kb * 8;
                float2 a00 = *(const float2*)(pA0 + ko);
                float2 a01 = *(const float2*)(pA0 + 8 * 36 + ko);
                float2 a10 = *(const float2*)(pA1 + ko);
                float2 a11 = *(const float2*)(pA1 + 8 * 36 + ko);
#pragma unroll
                for (int n8 = 0; n8 < 8; n8++) {
                    float2 bb = *(const float2*)(pB + n8 * 288 + ko);
                    mma_tf32(acc[0][n8], fu(a00.x), fu(a01.x), fu(a00.y), fu(a01.y),
                             fu(bb.x), fu(bb.y));
                    mma_tf32(acc[1][n8], fu(a10.x), fu(a11.x), fu(a10.y), fu(a11.y),
                             fu(bb.x), fu(bb.y));
                }
            }

            CP_WAIT0();
            __syncthreads();
        }
    }

    // ---- epilogue: BN + ReLU + store ----
    const float* s_sc = smem + SC_OFF;
    const float* s_sh = smem + SH_OFF;
    const int r0 = lane >> 2;
    const int cc = (lane & 3) * 2;
#pragma unroll
    for (int mt = 0; mt < 2; mt++) {
        const int y = y0 + 2 * wid + mt;
        if (PERM_OUT) {
            float* ob = out + ((size_t)b * 4096 + (y << 6) + x0) * 64;
#pragma unroll
            for (int nt = 0; nt < 8; nt++) {
#pragma unroll
                for (int j = 0; j < 4; j++) {
                    int oc = nt * 8 + cc + (j & 1);
                    int xo = r0 + (j >> 1) * 8;
                    float v = fmaxf(acc[mt][nt][j] * s_sc[oc] + s_sh[oc], 0.f);
                    int p3 = oc & 7;
                    int pp = (oc & ~7) | ((p3 < 4) ? 2 * p3 : 2 * (p3 - 4) + 1);
                    ob[(size_t)xo * 64 + pp] = tf32r(v);
                }
            }
        } else {
            float* po = out + (((size_t)b * 64) << 12) + (y << 6) + x0;
#pragma unroll
            for (int nt = 0; nt < 8; nt++) {
#pragma unroll
                for (int j = 0; j < 4; j++) {
                    int oc = nt * 8 + cc + (j & 1);
                    int xo = r0 + (j >> 1) * 8;
                    float v = acc[mt][nt][j] * s_sc[oc] + s_sh[oc];
                    po[((size_t)oc << 12) + xo] = fmaxf(v, 0.f);
                }
            }
        }
    }
}

// ---------------- global average pooling ----------------
__global__ void pool_kernel(const float* __restrict__ x, const float* __restrict__ ef) {
    const int c = blockIdx.x;
    const int b = blockIdx.y;
    const int tid = threadIdx.x;
    const float* src = (c < 256) ? &x[(size_t)((b << 8) + c) << 12]
                                 : &ef[(size_t)((b * 64) + (c - 256)) << 12];
    float s = 0.f;
    for (int i = tid; i < 4096; i += 128) s += src[i];
    __shared__ float red[128];
    red[tid] = s;
    __syncthreads();
    for (int o = 64; o > 0; o >>= 1) {
        if (tid < o) red[tid] += red[tid + o];
        __syncthreads();
    }
    if (tid == 0) g_pool[b * 320 + c] = red[0] * (1.f / 4096.f);
}

// ---------------- gate MLP ----------------
__global__ void gate_kernel(const float* __restrict__ g1_w, const float* __restrict__ g1_b,
                            const float* __restrict__ gbn_g, const float* __restrict__ gbn_b,
                            const float* __restrict__ gbn_m, const float* __restrict__ gbn_v,
                            const float* __restrict__ g2_w, const float* __restrict__ g2_b) {
    const int b = blockIdx.x;
    const int tid = threadIdx.x;
    __shared__ float sg[320];
    __shared__ float sh[128];
    for (int i = tid; i < 320; i += 128) sg[i] = g_pool[b * 320 + i];
    __syncthreads();
    {
        float s = 0.f;
        const float* wr = g1_w + tid * 320;
        for (int k = 0; k < 320; k++) s = fmaf(wr[k], sg[k], s);
        s += g1_b[tid];
        float inv = gbn_g[tid] * rsqrtf(gbn_v[tid] + BN_EPS);
        s = (s - gbn_m[tid]) * inv + gbn_b[tid];
        sh[tid] = fmaxf(s, 0.f);
    }
    __syncthreads();
    for (int oc = tid; oc < 256; oc += 128) {
        float t = 0.f;
        const float* wr = g2_w + oc * 128;
        for (int k = 0; k < 128; k++) t = fmaf(wr[k], sh[k], t);
        t += g2_b[oc];
        g_gate[b * 256 + oc] = 1.f / (1.f + expf(-t));
    }
}

// ---------------- 1x1 conv (64->256) + gated residual add ----------------
__global__ void out_gemm(const float* __restrict__ ef, const float* __restrict__ x,
                         const float* __restrict__ out_b, float* __restrict__ out) {
    __shared__ __align__(16) float s_ef[64 * 64];
    __shared__ __align__(16) float s_w[64 * 64];
    const int tid = threadIdx.x;
    const int px = tid & 63;
    const int ocq = tid >> 6;
    const int b = blockIdx.y;
    const int p0 = blockIdx.x * 64;

    for (int idx = tid; idx < 64 * 64; idx += 256) {
        int ic = idx >> 6, p = idx & 63;
        s_ef[(ic << 6) + p] = ef[((size_t)(b * 64 + ic) << 12) + p0 + p];
    }

    for (int ocg = 0; ocg < 4; ocg++) {
        __syncthreads();
        for (int idx = tid; idx < 64 * 64; idx += 256) {
            int ic = idx >> 6, ocl = idx & 63;
            s_w[(ic << 6) + ocl] = g_owt[(ic << 8) + ocg * 64 + ocl];
        }
        __syncthreads();

        unsigned long long acc[8];
        const unsigned long long z = pack2(0.f, 0.f);
#pragma unroll
        for (int i = 0; i < 8; i++) acc[i] = z;

        for (int ic = 0; ic < 64; ic++) {
            float v = s_ef[(ic << 6) + px];
            unsigned long long vv = pack2(v, v);
            const ulonglong2* wp = (const ulonglong2*)&s_w[(ic << 6) + (ocq << 4)];
#pragma unroll
            for (int j = 0; j < 4; j++) {
                ulonglong2 w2 = wp[j];
                fma2(acc[2 * j], vv, w2.x);
                fma2(acc[2 * j + 1], vv, w2.y);
            }
        }

#pragma unroll
        for (int i = 0; i < 8; i++) {
            float2 a = unpack2(acc[i]);
            int oc = ocg * 64 + (ocq << 4) + 2 * i;
            {
                size_t gi = ((size_t)((b << 8) + oc) << 12) + p0 + px;
                out[gi] = x[gi] + g_gate[b * 256 + oc] * (a.x + out_b[oc]);
            }
            {
                size_t gi = ((size_t)((b << 8) + oc + 1) << 12) + p0 + px;
                out[gi] = x[gi] + g_gate[b * 256 + oc + 1] * (a.y + out_b[oc + 1]);
            }
        }
    }
}

// ---------------- launch ----------------
extern "C" void kernel_launch(void* const* d_in, const int* in_sizes, int n_in,
                              void* d_out, int out_size) {
    const float* x     = (const float*)d_in[0];
    const float* ec1_w = (const float*)d_in[1];
    const float* ec1_b = (const float*)d_in[2];
    const float* bn1_g = (const float*)d_in[3];
    const float* bn1_b = (const float*)d_in[4];
    const float* bn1_m = (const float*)d_in[5];
    const float* bn1_v = (const float*)d_in[6];
    const float* ec2_w = (const float*)d_in[7];
    const float* ec2_b = (const float*)d_in[8];
    const float* bn2_g = (const float*)d_in[9];
    const float* bn2_b = (const float*)d_in[10];
    const float* bn2_m = (const float*)d_in[11];
    const float* bn2_v = (const float*)d_in[12];
    const float* g1_w  = (const float*)d_in[13];
    const float* g1_b  = (const float*)d_in[14];
    const float* gbn_g = (const float*)d_in[15];
    const float* gbn_b = (const float*)d_in[16];
    const float* gbn_m = (const float*)d_in[17];
    const float* gbn_v = (const float*)d_in[18];
    const float* g2_w  = (const float*)d_in[19];
    const float* g2_b  = (const float*)d_in[20];
    const float* out_w = (const float*)d_in[21];
    const float* out_b = (const float*)d_in[22];
    float* out = (float*)d_out;

    float *xt, *ef1, *ef, *w1t, *w2t;
    cudaGetSymbolAddress((void**)&xt,  g_xt);
    cudaGetSymbolAddress((void**)&ef1, g_ef1);
    cudaGetSymbolAddress((void**)&ef,  g_ef);
    cudaGetSymbolAddress((void**)&w1t, g_w1t);
    cudaGetSymbolAddress((void**)&w2t, g_w2t);
    float *sc1, *sh1, *sc2, *sh2;
    cudaGetSymbolAddress((void**)&sc1, g_sc1);
    cudaGetSymbolAddress((void**)&sh1, g_sh1);
    cudaGetSymbolAddress((void**)&sc2, g_sc2);
    cudaGetSymbolAddress((void**)&sh2, g_sh2);

    // 1: prep
    prep_kernel<<<576, 256>>>(ec1_w, ec1_b, bn1_g, bn1_b, bn1_m, bn1_v,
                              ec2_w, ec2_b, bn2_g, bn2_b, bn2_m, bn2_v, out_w);
    // 2-3: input transpose
    xt_kernel<<<dim3(32, 4, 8), 256>>>(x, 0);
    xt_kernel<<<dim3(32, 4, 8), 256>>>(x, 8);
    // 4: conv1 (tf32 MMA, async-pipelined) -> ef1 (perm layout)
    conv_mma<4, true><<<dim3(4, 8, 16), 128, SMEM_TOTAL>>>(xt, w1t, sc1, sh1, ef1);
    // 5: conv2 -> ef (std layout)
    conv_mma<1, false><<<dim3(4, 8, 16), 128, SMEM_TOTAL>>>(ef1, w2t, sc2, sh2, ef);
    // 6-8: pool, gate, output
    pool_kernel<<<dim3(320, 16), 128>>>(x, ef);
    gate_kernel<<<16, 128>>>(g1_w, g1_b, gbn_g, gbn_b, gbn_m, gbn_v, g2_w, g2_b);
    out_gemm<<<dim3(64, 16), 256>>>(ef, x, out_b, out);
}

// round 11
// speedup vs baseline: 3.4036x; 1.3232x over previous
#include <cuda_runtime.h>
#include <cstdint>
#include <math.h>

#define BN_EPS 1e-5f

// ---------------- device scratch (no allocations allowed) ----------------
__device__ __align__(16) float g_xt [16 * 4 * 4096 * 64]; // x: [b][g][px][64pos] tf32 perm
__device__ __align__(16) float g_ef1[16 * 4096 * 64];     // conv1 out [b][px][64pos]
__device__ __align__(16) float g_ef [16 * 4096 * 64];     // conv2 out [b][px][64pos]
__device__ __align__(16) float g_w1t[4 * 9 * 64 * 64];    // [g][t][oc][64pos] tf32
__device__ __align__(16) float g_w2t[9 * 64 * 64];        // [t][oc][64pos]
__device__ __align__(16) float g_owt[256 * 64];           // [oc][64pos] tf32
__device__ __align__(16) float g_g1t[320 * 128];          // g1_w transposed [k][h]
__device__ __align__(16) float g_g2t[128 * 256];          // g2_w transposed [k][o]
__device__ float g_sc1[64], g_sh1[64], g_sc2[64], g_sh2[64];
__device__ float g_xpp[16 * 256 * 32];                    // x-pool partials [b][c][chunk]
__device__ float g_epp[16 * 32 * 64];                     // ef-pool partials [b][tile][oc]
__device__ float g_gate[16 * 256];

// perm within each 16-block: pos(k) = (k%4)*4 + k/4  (4x4 transpose, self-inverse)
__device__ __host__ __forceinline__ int POS(int ic) {
    return (ic & ~15) | ((ic & 3) * 4 + ((ic >> 2) & 3));
}

__device__ __forceinline__ float tf32r(float x) {
    uint32_t u;
    asm("cvt.rna.tf32.f32 %0, %1;" : "=r"(u) : "f"(x));
    return __uint_as_float(u);
}
__device__ __forceinline__ uint32_t fu(float x) { return __float_as_uint(x); }

__device__ __forceinline__ uint32_t smem_u32(const void* p) {
    uint32_t a;
    asm("{ .reg .u64 t; cvta.to.shared.u64 t, %1; cvt.u32.u64 %0, t; }" : "=r"(a) : "l"(p));
    return a;
}

#define CP_ASYNC16(dst_u32, src_ptr) \
    asm volatile("cp.async.cg.shared.global [%0], [%1], 16;" :: "r"(dst_u32), "l"(src_ptr))
#define CP_COMMIT() asm volatile("cp.async.commit_group;" ::: "memory")
#define CP_WAIT0()  asm volatile("cp.async.wait_group 0;" ::: "memory")

__device__ __forceinline__ void mma_tf32(float (&c)[4], uint32_t a0, uint32_t a1,
                                         uint32_t a2, uint32_t a3, uint32_t b0, uint32_t b1) {
    asm volatile("mma.sync.aligned.m16n8k8.row.col.f32.tf32.tf32.f32 "
                 "{%0,%1,%2,%3}, {%4,%5,%6,%7}, {%8,%9}, {%0,%1,%2,%3};"
                 : "+f"(c[0]), "+f"(c[1]), "+f"(c[2]), "+f"(c[3])
                 : "r"(a0), "r"(a1), "r"(a2), "r"(a3), "r"(b0), "r"(b1));
}

// ---------------- prep: weight transposes (perm, tf32) + BN folding ----------------
__global__ void prep_kernel(const float* __restrict__ ec1_w, const float* __restrict__ ec1_b,
                            const float* __restrict__ bn1_g, const float* __restrict__ bn1_b,
                            const float* __restrict__ bn1_m, const float* __restrict__ bn1_v,
                            const float* __restrict__ ec2_w, const float* __restrict__ ec2_b,
                            const float* __restrict__ bn2_g, const float* __restrict__ bn2_b,
                            const float* __restrict__ bn2_m, const float* __restrict__ bn2_v,
                            const float* __restrict__ out_w, const float* __restrict__ g1_w,
                            const float* __restrict__ g2_w) {
    int j = blockIdx.x * blockDim.x + threadIdx.x;
    if (j < 4 * 9 * 64 * 64) {           // g_w1t[g][t][oc][pos]
        int pos = j & 63;
        int oc = (j >> 6) & 63;
        int gt = j >> 12;
        int t = gt % 9;
        int gq = gt / 9;
        g_w1t[j] = tf32r(ec1_w[(oc * 256 + gq * 64 + POS(pos)) * 9 + t]);
    }
    if (j < 9 * 64 * 64) {               // g_w2t[t][oc][pos]
        int pos = j & 63;
        int oc = (j >> 6) & 63;
        int t = j >> 12;
        g_w2t[j] = tf32r(ec2_w[(oc * 64 + POS(pos)) * 9 + t]);
    }
    if (j < 256 * 64) {                  // g_owt[oc][pos]
        int pos = j & 63;
        int oc = j >> 6;
        g_owt[j] = tf32r(out_w[oc * 64 + POS(pos)]);
    }
    if (j < 320 * 128) {                 // g1 transpose [k][h]
        int h = j & 127, k = j >> 7;
        g_g1t[j] = g1_w[h * 320 + k];
    }
    if (j < 128 * 256) {                 // g2 transpose [k][o]
        int o = j & 255, k = j >> 8;
        g_g2t[j] = g2_w[o * 128 + k];
    }
    if (j < 64) {
        float inv1 = bn1_g[j] * rsqrtf(bn1_v[j] + BN_EPS);
        g_sc1[j] = inv1;
        g_sh1[j] = ec1_b[j] * inv1 + bn1_b[j] - bn1_m[j] * inv1;
        float inv2 = bn2_g[j] * rsqrtf(bn2_v[j] + BN_EPS);
        g_sc2[j] = inv2;
        g_sh2[j] = ec2_b[j] * inv2 + bn2_b[j] - bn2_m[j] * inv2;
    }
}

// ---------------- input transpose + fused x-pool partials ----------------
__global__ void xt_kernel(const float* __restrict__ x, int b_base) {
    __shared__ float s[64 * 129];
    __shared__ float ps[64][4];
    const int ch = blockIdx.x;           // 128-px chunk
    const int g = blockIdx.y;
    const int b = b_base + blockIdx.z;
    const int tid = threadIdx.x;         // 256
    for (int idx = tid; idx < 64 * 128; idx += 256) {
        int ic = idx >> 7, px = idx & 127;
        s[ic * 129 + px] = x[((size_t)(b * 256 + g * 64 + ic) << 12) + ch * 128 + px];
    }
    __syncthreads();
    // pool partials over this chunk
    {
        int c = tid & 63, seg = tid >> 6;
        const float* row = s + c * 129 + seg * 32;
        float ss = 0.f;
#pragma unroll
        for (int i = 0; i < 32; i++) ss += row[i];
        ps[c][seg] = ss;
    }
    // transpose + perm + tf32
    float* dst = g_xt + ((size_t)(b * 4 + g) * 4096 + ch * 128) * 64;
    for (int jj = tid; jj < 128 * 16; jj += 256) {
        int px = jj >> 4, qu = jj & 15;
        int blk = qu >> 2, qq = qu & 3;
        const float* col = s + (blk * 16 + qq) * 129 + px;
        float4 v;
        v.x = tf32r(col[0 * 129]);
        v.y = tf32r(col[4 * 129]);
        v.z = tf32r(col[8 * 129]);
        v.w = tf32r(col[12 * 129]);
        *(float4*)(dst + px * 64 + blk * 16 + qq * 4) = v;
    }
    __syncthreads();
    if (tid < 64)
        g_xpp[((size_t)b * 256 + g * 64 + tid) * 32 + ch] =
            ps[tid][0] + ps[tid][1] + ps[tid][2] + ps[tid][3];
}

// ---------------- tf32 MMA conv3x3 + BN + ReLU (B from global, oc-split) ----------------
template <int GROUPS, bool POOL>
__global__ void __launch_bounds__(128, 5)
conv_mma(const float* __restrict__ xt, const float* __restrict__ wt,
         const float* __restrict__ scale, const float* __restrict__ shift,
         float* __restrict__ out) {
    __shared__ __align__(16) float sA[180 * 48];
    __shared__ float s_sc[64], s_sh[64];
    __shared__ float pbuf[4][32];
    const int tid = threadIdx.x;
    const int wid = tid >> 5, lane = tid & 31;
    const int lg = lane >> 2, q = lane & 3;
    const int bx = blockIdx.x;
    const int ocg = bx & 1;
    const int x0 = (bx >> 1) * 16, y0 = blockIdx.y * 8, b = blockIdx.z;
    const uint32_t sA32 = smem_u32(sA);

    if (tid < 64) { s_sc[tid] = scale[tid]; s_sh[tid] = shift[tid]; }

    float acc[2][4][4] = {};

    for (int ci = 0; ci < GROUPS * 2; ci++) {
        const int g = ci >> 1, h = ci & 1;
        __syncthreads();                 // prior chunk's A reads done
        // ---- stage A half-chunk [180 px][32pos] via cp.async ----
        const float* srcb = xt + ((size_t)(b * GROUPS + g) * 4096) * 64 + h * 32;
        for (int m = tid; m < 1440; m += 128) {
            int p = m >> 3, c = m & 7;
            int tr = p / 18, tc = p - tr * 18;
            int gy = y0 - 1 + tr, gx = x0 - 1 + tc;
            if ((unsigned)gy < 64u && (unsigned)gx < 64u)
                CP_ASYNC16(sA32 + (uint32_t)(p * 48 + c * 4) * 4,
                           srcb + ((gy << 6) + gx) * 64 + c * 4);
            else
                *(uint4*)(sA + p * 48 + c * 4) = make_uint4(0, 0, 0, 0);
        }
        CP_COMMIT();
        CP_WAIT0();
        __syncthreads();

        const float* wb = wt + (size_t)(g * 9) * 4096 + (ocg * 32 + lg) * 64 + h * 32 + q * 4;
        for (int t = 0; t < 9; t++) {     // barrier-free tap loop
            const int ky = t / 3, kx = t - 3 * ky;
            const float* pA0 = sA + ((2 * wid + ky) * 18 + kx + lg) * 48 + q * 4;
            const float* pA1 = pA0 + 18 * 48;
            const float* wtap = wb + (size_t)t * 4096;
#pragma unroll
            for (int pr = 0; pr < 2; pr++) {
                const int ko = pr * 16;
                float4 v00 = *(const float4*)(pA0 + ko);
                float4 v01 = *(const float4*)(pA0 + 8 * 48 + ko);
                float4 v10 = *(const float4*)(pA1 + ko);
                float4 v11 = *(const float4*)(pA1 + 8 * 48 + ko);
#pragma unroll
                for (int n8 = 0; n8 < 4; n8++) {
                    float4 bv = __ldg((const float4*)(wtap + n8 * 512 + ko));
                    mma_tf32(acc[0][n8], fu(v00.x), fu(v01.x), fu(v00.y), fu(v01.y),
                             fu(bv.x), fu(bv.y));
                    mma_tf32(acc[0][n8], fu(v00.z), fu(v01.z), fu(v00.w), fu(v01.w),
                             fu(bv.z), fu(bv.w));
                    mma_tf32(acc[1][n8], fu(v10.x), fu(v11.x), fu(v10.y), fu(v11.y),
                             fu(bv.x), fu(bv.y));
                    mma_tf32(acc[1][n8], fu(v10.z), fu(v11.z), fu(v10.w), fu(v11.w),
                             fu(bv.z), fu(bv.w));
                }
            }
        }
    }

    // ---- epilogue: BN + ReLU + perm store (+ pool partials) ----
    float pl[4][2] = {};
#pragma unroll
    for (int mt = 0; mt < 2; mt++) {
        const int y = y0 + 2 * wid + mt;
        float* ob = out + ((size_t)b * 4096 + (y << 6) + x0) * 64;
#pragma unroll
        for (int n8 = 0; n8 < 4; n8++) {
#pragma unroll
            for (int j = 0; j < 4; j++) {
                int oc = ocg * 32 + n8 * 8 + q * 2 + (j & 1);
                int xo = lg + (j >> 1) * 8;
                float v = fmaxf(acc[mt][n8][j] * s_sc[oc] + s_sh[oc], 0.f);
                if (POOL) pl[n8][j & 1] += v;
                ob[(size_t)xo * 64 + POS(oc)] = tf32r(v);
            }
        }
    }
    if (POOL) {
#pragma unroll
        for (int n8 = 0; n8 < 4; n8++) {
#pragma unroll
            for (int jp = 0; jp < 2; jp++) {
                float s = pl[n8][jp];
                s += __shfl_xor_sync(0xffffffffu, s, 16);
                s += __shfl_xor_sync(0xffffffffu, s, 8);
                s += __shfl_xor_sync(0xffffffffu, s, 4);
                if (lg == 0) pbuf[wid][n8 * 8 + q * 2 + jp] = s;
            }
        }
        __syncthreads();
        if (tid < 32) {
            float s = pbuf[0][tid] + pbuf[1][tid] + pbuf[2][tid] + pbuf[3][tid];
            int tile = blockIdx.y * 4 + (bx >> 1);
            g_epp[((size_t)b * 32 + tile) * 64 + ocg * 32 + tid] = s;
        }
    }
}

// ---------------- gate MLP (reduces pool partials) ----------------
__global__ void gate_kernel(const float* __restrict__ g1_b,
                            const float* __restrict__ gbn_g, const float* __restrict__ gbn_b,
                            const float* __restrict__ gbn_m, const float* __restrict__ gbn_v,
                            const float* __restrict__ g2_b) {
    const int b = blockIdx.x;
    const int tid = threadIdx.x;         // 128
    __shared__ float sg[320];
    __shared__ float sh[128];
    for (int c = tid; c < 256; c += 128) {
        const float* pp = g_xpp + ((size_t)b * 256 + c) * 32;
        float s = 0.f;
#pragma unroll
        for (int i = 0; i < 32; i++) s += pp[i];
        sg[c] = s * (1.f / 4096.f);
    }
    if (tid < 64) {
        float s = 0.f;
#pragma unroll
        for (int t = 0; t < 32; t++) s += g_epp[((size_t)b * 32 + t) * 64 + tid];
        sg[256 + tid] = s * (1.f / 4096.f);
    }
    __syncthreads();
    {
        float s = 0.f;
        for (int k = 0; k < 320; k++) s = fmaf(g_g1t[k * 128 + tid], sg[k], s);
        s += g1_b[tid];
        float inv = gbn_g[tid] * rsqrtf(gbn_v[tid] + BN_EPS);
        s = (s - gbn_m[tid]) * inv + gbn_b[tid];
        sh[tid] = fmaxf(s, 0.f);
    }
    __syncthreads();
    for (int oc = tid; oc < 256; oc += 128) {
        float s = 0.f;
        for (int k = 0; k < 128; k++) s = fmaf(g_g2t[k * 256 + oc], sh[k], s);
        s += g2_b[oc];
        g_gate[b * 256 + oc] = 1.f / (1.f + expf(-s));
    }
}

// ---------------- 1x1 conv (64->256) via tf32 MMA + gated residual ----------------
__global__ void __launch_bounds__(128, 4)
out_gemm(const float* __restrict__ ef, const float* __restrict__ x,
         const float* __restrict__ out_b, float* __restrict__ out) {
    __shared__ __align__(16) float sA[128 * 80];
    const int tid = threadIdx.x;
    const int wid = tid >> 5, lane = tid & 31;
    const int lg = lane >> 2, q = lane & 3;
    const int p0 = blockIdx.x * 128, b = blockIdx.y;
    const uint32_t sA32 = smem_u32(sA);

    const float* src = ef + ((size_t)b * 4096 + p0) * 64;
    for (int m = tid; m < 2048; m += 128) {
        int p = m >> 4, c = m & 15;
        CP_ASYNC16(sA32 + (uint32_t)(p * 80 + c * 4) * 4, src + p * 64 + c * 4);
    }
    CP_COMMIT();
    CP_WAIT0();
    __syncthreads();

    const int rbase = 32 * wid + lg;
    for (int ocg = 0; ocg < 8; ocg++) {
        float acc[2][4][4] = {};
        const float* wb = g_owt + (ocg * 32 + lg) * 64 + q * 4;
#pragma unroll
        for (int pr = 0; pr < 4; pr++) {
            const int ko = pr * 16 + q * 4;   // thread-in-group channel offset
            float4 v00 = *(const float4*)(sA + (rbase) * 80 + ko);
            float4 v01 = *(const float4*)(sA + (rbase + 8) * 80 + ko);
            float4 v10 = *(const float4*)(sA + (rbase + 16) * 80 + ko);
            float4 v11 = *(const float4*)(sA + (rbase + 24) * 80 + ko);
#pragma unroll
            for (int n8 = 0; n8 < 4; n8++) {
                float4 bv = __ldg((const float4*)(wb + n8 * 512 + pr * 16));
                mma_tf32(acc[0][n8], fu(v00.x), fu(v01.x), fu(v00.y), fu(v01.y),
                         fu(bv.x), fu(bv.y));
                mma_tf32(acc[0][n8], fu(v00.z), fu(v01.z), fu(v00.w), fu(v01.w),
                         fu(bv.z), fu(bv.w));
                mma_tf32(acc[1][n8], fu(v10.x), fu(v11.x), fu(v10.y), fu(v11.y),
                         fu(bv.x), fu(bv.y));
                mma_tf32(acc[1][n8], fu(v10.z), fu(v11.z), fu(v10.w), fu(v11.w),
                         fu(bv.z), fu(bv.w));
            }
        }
#pragma unroll
        for (int n8 = 0; n8 < 4; n8++) {
#pragma unroll
            for (int jp = 0; jp < 2; jp++) {
                const int oc = ocg * 32 + n8 * 8 + q * 2 + jp;
                const float gg = g_gate[b * 256 + oc];
                const float bb = out_b[oc];
                const size_t rowo = ((size_t)(b * 256 + oc)) << 12;
#pragma unroll
                for (int mt = 0; mt < 2; mt++) {
#pragma unroll
                    for (int jh = 0; jh < 2; jh++) {
                        int px = p0 + 32 * wid + mt * 16 + lg + jh * 8;
                        out[rowo + px] = x[rowo + px] + gg * (acc[mt][n8][jh * 2 + jp] + bb);
                    }
                }
            }
        }
    }
}

// ---------------- launch ----------------
extern "C" void kernel_launch(void* const* d_in, const int* in_sizes, int n_in,
                              void* d_out, int out_size) {
    const float* x     = (const float*)d_in[0];
    const float* ec1_w = (const float*)d_in[1];
    const float* ec1_b = (const float*)d_in[2];
    const float* bn1_g = (const float*)d_in[3];
    const float* bn1_b = (const float*)d_in[4];
    const float* bn1_m = (const float*)d_in[5];
    const float* bn1_v = (const float*)d_in[6];
    const float* ec2_w = (const float*)d_in[7];
    const float* ec2_b = (const float*)d_in[8];
    const float* bn2_g = (const float*)d_in[9];
    const float* bn2_b = (const float*)d_in[10];
    const float* bn2_m = (const float*)d_in[11];
    const float* bn2_v = (const float*)d_in[12];
    const float* g1_w  = (const float*)d_in[13];
    const float* g1_b  = (const float*)d_in[14];
    const float* gbn_g = (const float*)d_in[15];
    const float* gbn_b = (const float*)d_in[16];
    const float* gbn_m = (const float*)d_in[17];
    const float* gbn_v = (const float*)d_in[18];
    const float* g2_w  = (const float*)d_in[19];
    const float* g2_b  = (const float*)d_in[20];
    const float* out_w = (const float*)d_in[21];
    const float* out_b = (const float*)d_in[22];
    float* out = (float*)d_out;

    float *xt, *ef1, *ef, *w1t, *w2t;
    cudaGetSymbolAddress((void**)&xt,  g_xt);
    cudaGetSymbolAddress((void**)&ef1, g_ef1);
    cudaGetSymbolAddress((void**)&ef,  g_ef);
    cudaGetSymbolAddress((void**)&w1t, g_w1t);
    cudaGetSymbolAddress((void**)&w2t, g_w2t);
    float *sc1, *sh1, *sc2, *sh2;
    cudaGetSymbolAddress((void**)&sc1, g_sc1);
    cudaGetSymbolAddress((void**)&sh1, g_sh1);
    cudaGetSymbolAddress((void**)&sc2, g_sc2);
    cudaGetSymbolAddress((void**)&sh2, g_sh2);

    // 1: prep
    prep_kernel<<<576, 256>>>(ec1_w, ec1_b, bn1_g, bn1_b, bn1_m, bn1_v,
                              ec2_w, ec2_b, bn2_g, bn2_b, bn2_m, bn2_v,
                              out_w, g1_w, g2_w);
    // 2-3: input transpose + x-pool partials
    xt_kernel<<<dim3(32, 4, 8), 256>>>(x, 0);
    xt_kernel<<<dim3(32, 4, 8), 256>>>(x, 8);
    // 4: conv1 -> ef1 (perm layout)
    conv_mma<4, false><<<dim3(8, 8, 16), 128>>>(xt, w1t, sc1, sh1, ef1);
    // 5: conv2 -> ef (perm layout) + ef-pool partials
    conv_mma<1, true><<<dim3(8, 8, 16), 128>>>(ef1, w2t, sc2, sh2, ef);
    // 6: gate (reduces pool partials)
    gate_kernel<<<16, 128>>>(g1_b, gbn_g, gbn_b, gbn_m, gbn_v, g2_b);
    // 7: output GEMM + gated residual
    out_gemm<<<dim3(32, 16), 128>>>(ef, x, out_b, out);
}